// round 1
// baseline (speedup 1.0000x reference)
#include <cuda_runtime.h>
#include <cstdint>

// 12-bit ripple-carry adder over {0,1}-valued float32 arrays.
// A,B: [BATCH, 12] float32. Bit index 11 is the LSB (weight 2^(11-i) for col i).
// Output: sums [BATCH,12] flattened at d_out[0..BATCH*12), carry [BATCH,1] at
// d_out[BATCH*12..BATCH*13).
//
// Strategy: pack row -> 12-bit uint, integer add, unpack 13 bits to floats.
// Pure HBM-bound streaming: 3x float4 loads per operand per row, 3x float4
// stores + 1 scalar store per row. All 16B-aligned (48B rows).

#ifndef BATCH_N
#define BATCH_N 4194304
#endif

__device__ __forceinline__ unsigned f2b(float x) {
    // x is exactly 0.0f or 1.0f
    return __float_as_uint(x) != 0u ? 1u : 0u;
}

__device__ __forceinline__ float b2f(unsigned v, int k) {
    return ((v >> k) & 1u) ? 1.0f : 0.0f;
}

__global__ void __launch_bounds__(256) adder12_kernel(
    const float4* __restrict__ A4,
    const float4* __restrict__ B4,
    float4* __restrict__ S4,      // sums, [BATCH,12] as float4[BATCH*3]
    float* __restrict__ carry,    // [BATCH]
    int batch)
{
    int row = blockIdx.x * blockDim.x + threadIdx.x;
    if (row >= batch) return;

    long base = (long)row * 3;
    float4 a0 = A4[base + 0];
    float4 a1 = A4[base + 1];
    float4 a2 = A4[base + 2];
    float4 b0 = B4[base + 0];
    float4 b1 = B4[base + 1];
    float4 b2 = B4[base + 2];

    // Column i has weight 2^(11-i). Columns 0..3 in v0, 4..7 in v1, 8..11 in v2.
    unsigned av =
        (f2b(a0.x) << 11) | (f2b(a0.y) << 10) | (f2b(a0.z) << 9) | (f2b(a0.w) << 8) |
        (f2b(a1.x) << 7)  | (f2b(a1.y) << 6)  | (f2b(a1.z) << 5) | (f2b(a1.w) << 4) |
        (f2b(a2.x) << 3)  | (f2b(a2.y) << 2)  | (f2b(a2.z) << 1) | (f2b(a2.w) << 0);
    unsigned bv =
        (f2b(b0.x) << 11) | (f2b(b0.y) << 10) | (f2b(b0.z) << 9) | (f2b(b0.w) << 8) |
        (f2b(b1.x) << 7)  | (f2b(b1.y) << 6)  | (f2b(b1.z) << 5) | (f2b(b1.w) << 4) |
        (f2b(b2.x) << 3)  | (f2b(b2.y) << 2)  | (f2b(b2.z) << 1) | (f2b(b2.w) << 0);

    unsigned s = av + bv;  // 13-bit result

    float4 o0, o1, o2;
    o0.x = b2f(s, 11); o0.y = b2f(s, 10); o0.z = b2f(s, 9); o0.w = b2f(s, 8);
    o1.x = b2f(s, 7);  o1.y = b2f(s, 6);  o1.z = b2f(s, 5); o1.w = b2f(s, 4);
    o2.x = b2f(s, 3);  o2.y = b2f(s, 2);  o2.z = b2f(s, 1); o2.w = b2f(s, 0);

    S4[base + 0] = o0;
    S4[base + 1] = o1;
    S4[base + 2] = o2;
    carry[row] = b2f(s, 12);
}

extern "C" void kernel_launch(void* const* d_in, const int* in_sizes, int n_in,
                              void* d_out, int out_size) {
    const float* A = (const float*)d_in[0];
    const float* B = (const float*)d_in[1];
    float* out = (float*)d_out;

    int batch = in_sizes[0] / 12;  // element count of A = BATCH*12

    float* sums = out;                       // [batch*12]
    float* carry = out + (long)batch * 12;   // [batch]

    int threads = 256;
    int blocks = (batch + threads - 1) / threads;
    adder12_kernel<<<blocks, threads>>>(
        (const float4*)A, (const float4*)B, (float4*)sums, carry, batch);
}

// round 2
// speedup vs baseline: 1.0221x; 1.0221x over previous
#include <cuda_runtime.h>
#include <cstdint>

// 12-bit ripple-carry adder over {0,1}-valued float32 arrays.
// A,B: [BATCH, 12] float32, col 11 = LSB (weight 2^(11-i)).
// Out: sums [BATCH,12] at d_out[0..B*12), carry [BATCH] at d_out[B*12..B*13).
//
// Coalescing-first layout: thread t loads/stores float4 chunk t (contiguous
// warp-wide 512B transactions). Row assembly (3 chunks -> 12-bit int) goes
// through a 1.5KB smem nibble exchange. Block = 384 threads = 128 rows.

__device__ __forceinline__ unsigned f2b(float x) {
    return __float_as_uint(x) != 0u ? 1u : 0u;   // x is exactly 0.0f or 1.0f
}

__global__ void __launch_bounds__(384) adder12_kernel(
    const float4* __restrict__ A4,
    const float4* __restrict__ B4,
    float4* __restrict__ S4,      // sums, float4[batch*3]
    float* __restrict__ carry,    // [batch]
    int nchunks,                  // batch*3
    int batch)
{
    __shared__ unsigned nib[384]; // per-chunk: a-nibble | (b-nibble << 4)

    int t = blockIdx.x * 384 + threadIdx.x;
    bool valid = (t < nchunks);

    unsigned packed = 0;
    if (valid) {
        float4 a = A4[t];
        float4 b = B4[t];
        unsigned na = (f2b(a.x) << 3) | (f2b(a.y) << 2) | (f2b(a.z) << 1) | f2b(a.w);
        unsigned nb = (f2b(b.x) << 3) | (f2b(b.y) << 2) | (f2b(b.z) << 1) | f2b(b.w);
        packed = na | (nb << 4);
    }
    nib[threadIdx.x] = packed;
    __syncthreads();

    // Row-local sum for the row containing chunk threadIdx.x.
    int lrow = threadIdx.x / 3;          // 0..127
    int part = threadIdx.x - lrow * 3;   // 0..2 (chunk within row)
    int rb = lrow * 3;
    unsigned c0 = nib[rb + 0], c1 = nib[rb + 1], c2 = nib[rb + 2];
    // chunk j holds bit-weights: j=0 -> bits 11..8, j=1 -> 7..4, j=2 -> 3..0
    unsigned av = ((c0 & 0xF) << 8) | ((c1 & 0xF) << 4) | (c2 & 0xF);
    unsigned bv = ((c0 >> 4) << 8)  | (((c1 >> 4) & 0xF) << 4) | ((c2 >> 4) & 0xF);
    unsigned s = av + bv;                // 13-bit result

    if (valid) {
        unsigned sh = 8 - 4 * part;      // this chunk's nibble of the sum
        unsigned on = (s >> sh) & 0xF;
        float4 o;
        o.x = (on & 8u) ? 1.0f : 0.0f;
        o.y = (on & 4u) ? 1.0f : 0.0f;
        o.z = (on & 2u) ? 1.0f : 0.0f;
        o.w = (on & 1u) ? 1.0f : 0.0f;
        S4[t] = o;
    }

    // Carry-out: threads 0..127 each recompute one row's sum (smem is cheap)
    // and store coalesced.
    if (threadIdx.x < 128) {
        int row = blockIdx.x * 128 + threadIdx.x;
        if (row < batch) {
            int rb2 = threadIdx.x * 3;
            unsigned d0 = nib[rb2 + 0], d1 = nib[rb2 + 1], d2 = nib[rb2 + 2];
            unsigned av2 = ((d0 & 0xF) << 8) | ((d1 & 0xF) << 4) | (d2 & 0xF);
            unsigned bv2 = ((d0 >> 4) << 8)  | (((d1 >> 4) & 0xF) << 4) | ((d2 >> 4) & 0xF);
            unsigned s2 = av2 + bv2;
            carry[row] = (s2 >> 12) ? 1.0f : 0.0f;
        }
    }
}

extern "C" void kernel_launch(void* const* d_in, const int* in_sizes, int n_in,
                              void* d_out, int out_size) {
    const float* A = (const float*)d_in[0];
    const float* B = (const float*)d_in[1];
    float* out = (float*)d_out;

    int batch = in_sizes[0] / 12;
    int nchunks = batch * 3;

    float* sums = out;
    float* carry = out + (long)batch * 12;

    int threads = 384;
    int blocks = (nchunks + threads - 1) / threads;
    adder12_kernel<<<blocks, threads>>>(
        (const float4*)A, (const float4*)B, (float4*)sums, carry, nchunks, batch);
}